// round 1
// baseline (speedup 1.0000x reference)
#include <cuda_runtime.h>
#include <cuda_bf16.h>
#include <math.h>

// Problem constants (fixed shapes from reference setup_inputs)
#define WW 1920
#define HH 1080
#define CC 3
#define BB 4
#define HWN (HH * WW)            // 2,073,600
#define NN  (BB * HWN)           // 8,294,400
#define MOTION_TH_I 25           // 0.25 * D_SCALE_INT

// Scratch (allocation-free rule: __device__ globals)
__device__ int   g_dbuf[NN];
__device__ float g_wght[NN];

struct Corners {
    int   valid;      // 0/1
    int   d;          // depth int
    float k[4];       // nw, ne, sw, se
    int   idx[4];     // flat pixel index within batch image (y*W + x), clipped
};

__device__ __forceinline__ Corners compute_corners(float fx, float fy, int x, int y)
{
    Corners c;
    float xd = (float)x + fx;
    float yd = (float)y + fy;

    float magsq = fx * fx + fy * fy;
    c.d = (int)(100.0f * sqrtf(magsq));

    int xf = (int)floorf(xd);
    int yf = (int)floorf(yd);
    int xc = xf + 1;
    int yc = yf + 1;

    c.valid = (xf >= 0) & (xc <= WW) & (yf >= 0) & (yc <= HH);

    // weights exactly as reference: use float casts of int corners
    float xf_f = (float)xf, yf_f = (float)yf;
    float xc_f = (float)xc, yc_f = (float)yc;
    float wx1 = xc_f - xd;   // toward floor-x
    float wx0 = xd - xf_f;   // toward ceil-x
    float wy1 = yc_f - yd;
    float wy0 = yd - yf_f;
    c.k[0] = wx1 * wy1;  // nw
    c.k[1] = wx0 * wy1;  // ne
    c.k[2] = wx1 * wy0;  // sw
    c.k[3] = wx0 * wy0;  // se

    // clipped indices (under valid: xf in [0,W-1], xc may == W)
    int xfc = min(max(xf, 0), WW - 1);
    int yfc = min(max(yf, 0), HH - 1);
    int xcc = min(max(xc, 0), WW - 1);
    int ycc = min(max(yc, 0), HH - 1);
    c.idx[0] = yfc * WW + xfc;
    c.idx[1] = yfc * WW + xcc;
    c.idx[2] = ycc * WW + xfc;
    c.idx[3] = ycc * WW + xcc;
    return c;
}

__global__ void scatter_max_kernel(const float2* __restrict__ flow)
{
    int i = blockIdx.x * blockDim.x + threadIdx.x;
    if (i >= NN) return;
    int b = i / HWN;
    int p = i - b * HWN;
    int y = p / WW;
    int x = p - y * WW;

    float2 f = flow[i];
    Corners c = compute_corners(f.x, f.y, x, y);
    if (!c.valid) return;

    int base = b * HWN;
    #pragma unroll
    for (int j = 0; j < 4; j++) {
        if (c.k[j] >= 0.25f) {
            atomicMax(&g_dbuf[base + c.idx[j]], c.d);
        }
    }
}

__global__ void splat_kernel(const float* __restrict__ im0,
                             const float2* __restrict__ flow,
                             float* __restrict__ out)
{
    int i = blockIdx.x * blockDim.x + threadIdx.x;
    if (i >= NN) return;
    int b = i / HWN;
    int p = i - b * HWN;
    int y = p / WW;
    int x = p - y * WW;

    float2 f = flow[i];
    Corners c = compute_corners(f.x, f.y, x, y);
    if (!c.valid) return;

    int base = b * HWN;
    // load the 3 source channel values once
    const float* im0b = im0 + (size_t)b * CC * HWN + p;
    float v0 = im0b[0 * HWN];
    float v1 = im0b[1 * HWN];
    float v2 = im0b[2 * HWN];

    float* outb = out + (size_t)b * CC * HWN;

    #pragma unroll
    for (int j = 0; j < 4; j++) {
        float k = c.k[j];
        if (k >= 0.25f) {
            int ci = base + c.idx[j];
            int dg = g_dbuf[ci];
            if (dg - c.d <= MOTION_TH_I) {
                int oi = c.idx[j];
                atomicAdd(&outb[0 * HWN + oi], v0 * k);
                atomicAdd(&outb[1 * HWN + oi], v1 * k);
                atomicAdd(&outb[2 * HWN + oi], v2 * k);
                atomicAdd(&g_wght[ci], k);
            }
        }
    }
}

__global__ void normalize_kernel(float* __restrict__ out)
{
    int i = blockIdx.x * blockDim.x + threadIdx.x;
    if (i >= NN) return;
    int b = i / HWN;
    int p = i - b * HWN;

    float w = g_wght[i] / 3.0f;
    float m = fmaxf(w, 1e-5f);
    float inv = 1.0f / m;

    float* outb = out + (size_t)b * CC * HWN + p;
    outb[0 * HWN] *= inv;
    outb[1 * HWN] *= inv;
    outb[2 * HWN] *= inv;
}

extern "C" void kernel_launch(void* const* d_in, const int* in_sizes, int n_in,
                              void* d_out, int out_size)
{
    const float*  im0  = (const float*)d_in[0];
    const float2* flow = (const float2*)d_in[1];
    float* out = (float*)d_out;

    void *pd = nullptr, *pw = nullptr;
    cudaGetSymbolAddress(&pd, g_dbuf);
    cudaGetSymbolAddress(&pw, g_wght);

    cudaMemsetAsync(pd, 0, (size_t)NN * sizeof(int));
    cudaMemsetAsync(pw, 0, (size_t)NN * sizeof(float));
    cudaMemsetAsync(out, 0, (size_t)out_size * sizeof(float));

    const int T = 256;
    const int G = (NN + T - 1) / T;
    scatter_max_kernel<<<G, T>>>(flow);
    splat_kernel<<<G, T>>>(im0, flow, out);
    normalize_kernel<<<G, T>>>(out);
}

// round 2
// speedup vs baseline: 1.4391x; 1.4391x over previous
#include <cuda_runtime.h>
#include <cuda_bf16.h>
#include <math.h>

// Problem constants (fixed shapes from reference setup_inputs)
#define WW 1920
#define HH 1080
#define CC 3
#define BB 4
#define HWN (HH * WW)            // 2,073,600
#define NN  (BB * HWN)           // 8,294,400
#define MOTION_TH_I 25           // 0.25 * D_SCALE_INT

// Scratch (allocation-free rule: __device__ globals)
__device__ int    g_dbuf[NN];
__device__ float4 g_acc[NN];     // [c0, c1, c2, weight] per destination pixel

struct Corners {
    int   valid;      // 0/1
    int   d;          // depth int
    float k[4];       // nw, ne, sw, se
    int   idx[4];     // flat pixel index within batch image (y*W + x), clipped
};

__device__ __forceinline__ Corners compute_corners(float fx, float fy, int x, int y)
{
    Corners c;
    float xd = (float)x + fx;
    float yd = (float)y + fy;

    float magsq = fx * fx + fy * fy;
    c.d = (int)(100.0f * sqrtf(magsq));

    int xf = (int)floorf(xd);
    int yf = (int)floorf(yd);
    int xc = xf + 1;
    int yc = yf + 1;

    c.valid = (xf >= 0) & (xc <= WW) & (yf >= 0) & (yc <= HH);

    // weights exactly as reference: use float casts of int corners
    float xf_f = (float)xf, yf_f = (float)yf;
    float xc_f = (float)xc, yc_f = (float)yc;
    float wx1 = xc_f - xd;   // toward floor-x
    float wx0 = xd - xf_f;   // toward ceil-x
    float wy1 = yc_f - yd;
    float wy0 = yd - yf_f;
    c.k[0] = wx1 * wy1;  // nw
    c.k[1] = wx0 * wy1;  // ne
    c.k[2] = wx1 * wy0;  // sw
    c.k[3] = wx0 * wy0;  // se

    // clipped indices (under valid: xf in [0,W-1], xc may == W)
    int xfc = min(max(xf, 0), WW - 1);
    int yfc = min(max(yf, 0), HH - 1);
    int xcc = min(max(xc, 0), WW - 1);
    int ycc = min(max(yc, 0), HH - 1);
    c.idx[0] = yfc * WW + xfc;
    c.idx[1] = yfc * WW + xcc;
    c.idx[2] = ycc * WW + xfc;
    c.idx[3] = ycc * WW + xcc;
    return c;
}

__device__ __forceinline__ void red_add_v4(float4* addr, float a, float b, float cc, float dd)
{
    asm volatile("red.global.add.v4.f32 [%0], {%1, %2, %3, %4};"
                 :: "l"(addr), "f"(a), "f"(b), "f"(cc), "f"(dd)
                 : "memory");
}

__global__ void scatter_max_kernel(const float2* __restrict__ flow)
{
    int i = blockIdx.x * blockDim.x + threadIdx.x;
    if (i >= NN) return;
    int b = i / HWN;
    int p = i - b * HWN;
    int y = p / WW;
    int x = p - y * WW;

    float2 f = flow[i];
    Corners c = compute_corners(f.x, f.y, x, y);
    if (!c.valid) return;

    int base = b * HWN;
    #pragma unroll
    for (int j = 0; j < 4; j++) {
        if (c.k[j] >= 0.25f) {
            atomicMax(&g_dbuf[base + c.idx[j]], c.d);
        }
    }
}

__global__ void splat_kernel(const float* __restrict__ im0,
                             const float2* __restrict__ flow)
{
    int i = blockIdx.x * blockDim.x + threadIdx.x;
    if (i >= NN) return;
    int b = i / HWN;
    int p = i - b * HWN;
    int y = p / WW;
    int x = p - y * WW;

    float2 f = flow[i];
    Corners c = compute_corners(f.x, f.y, x, y);
    if (!c.valid) return;

    int base = b * HWN;
    // load the 3 source channel values once
    const float* im0b = im0 + (size_t)b * CC * HWN + p;
    float v0 = __ldg(&im0b[0 * HWN]);
    float v1 = __ldg(&im0b[1 * HWN]);
    float v2 = __ldg(&im0b[2 * HWN]);

    #pragma unroll
    for (int j = 0; j < 4; j++) {
        float k = c.k[j];
        if (k >= 0.25f) {
            int ci = base + c.idx[j];
            int dg = g_dbuf[ci];
            if (dg - c.d <= MOTION_TH_I) {
                red_add_v4(&g_acc[ci], v0 * k, v1 * k, v2 * k, k);
            }
        }
    }
}

__global__ void normalize_kernel(float* __restrict__ out)
{
    int i = blockIdx.x * blockDim.x + threadIdx.x;
    if (i >= NN) return;
    int b = i / HWN;
    int p = i - b * HWN;

    float4 a = g_acc[i];
    float w = a.w / 3.0f;
    float m = fmaxf(w, 1e-5f);
    float inv = 1.0f / m;

    float* outb = out + (size_t)b * CC * HWN + p;
    outb[0 * HWN] = a.x * inv;
    outb[1 * HWN] = a.y * inv;
    outb[2 * HWN] = a.z * inv;
}

extern "C" void kernel_launch(void* const* d_in, const int* in_sizes, int n_in,
                              void* d_out, int out_size)
{
    const float*  im0  = (const float*)d_in[0];
    const float2* flow = (const float2*)d_in[1];
    float* out = (float*)d_out;

    void *pd = nullptr, *pa = nullptr;
    cudaGetSymbolAddress(&pd, g_dbuf);
    cudaGetSymbolAddress(&pa, g_acc);

    cudaMemsetAsync(pd, 0, (size_t)NN * sizeof(int));
    cudaMemsetAsync(pa, 0, (size_t)NN * sizeof(float4));

    const int T = 256;
    const int G = (NN + T - 1) / T;
    scatter_max_kernel<<<G, T>>>(flow);
    splat_kernel<<<G, T>>>(im0, flow);
    normalize_kernel<<<G, T>>>(out);
}

// round 3
// speedup vs baseline: 1.5394x; 1.0697x over previous
#include <cuda_runtime.h>
#include <cuda_bf16.h>
#include <math.h>

// Problem constants (fixed shapes from reference setup_inputs)
#define WW 1920
#define HH 1080
#define CC 3
#define BB 4
#define HWN (HH * WW)            // 2,073,600
#define NN  (BB * HWN)           // 8,294,400
#define MOTION_TH_I 25           // 0.25 * D_SCALE_INT

// Scratch (allocation-free rule: __device__ globals)
__device__ int    g_dbuf[NN];
__device__ float4 g_acc[NN];     // [c0, c1, c2, weight] per destination pixel

struct Corners {
    int   valid;      // 0/1
    int   d;          // depth int
    float k[4];       // nw, ne, sw, se
    int   idx[4];     // flat pixel index within batch image (y*W + x), clipped
};

__device__ __forceinline__ Corners compute_corners(float fx, float fy, int x, int y)
{
    Corners c;
    float xd = (float)x + fx;
    float yd = (float)y + fy;

    float magsq = fx * fx + fy * fy;
    c.d = (int)(100.0f * sqrtf(magsq));

    int xf = (int)floorf(xd);
    int yf = (int)floorf(yd);
    int xc = xf + 1;
    int yc = yf + 1;

    c.valid = (xf >= 0) & (xc <= WW) & (yf >= 0) & (yc <= HH);

    // weights exactly as reference: use float casts of int corners
    float xf_f = (float)xf, yf_f = (float)yf;
    float xc_f = (float)xc, yc_f = (float)yc;
    float wx1 = xc_f - xd;   // toward floor-x
    float wx0 = xd - xf_f;   // toward ceil-x
    float wy1 = yc_f - yd;
    float wy0 = yd - yf_f;
    c.k[0] = wx1 * wy1;  // nw
    c.k[1] = wx0 * wy1;  // ne
    c.k[2] = wx1 * wy0;  // sw
    c.k[3] = wx0 * wy0;  // se

    // clipped indices (under valid: xf in [0,W-1], xc may == W)
    int xfc = min(max(xf, 0), WW - 1);
    int yfc = min(max(yf, 0), HH - 1);
    int xcc = min(max(xc, 0), WW - 1);
    int ycc = min(max(yc, 0), HH - 1);
    c.idx[0] = yfc * WW + xfc;
    c.idx[1] = yfc * WW + xcc;
    c.idx[2] = ycc * WW + xfc;
    c.idx[3] = ycc * WW + xcc;
    return c;
}

__device__ __forceinline__ void red_add_v4(float4* addr, float a, float b, float cc, float dd)
{
    asm volatile("red.global.add.v4.f32 [%0], {%1, %2, %3, %4};"
                 :: "l"(addr), "f"(a), "f"(b), "f"(cc), "f"(dd)
                 : "memory");
}

// grid: (15, 1080, 4), block: 128  -> x covers [0,1920) exactly
__global__ void __launch_bounds__(128) scatter_max_kernel(const float2* __restrict__ flow)
{
    int x = blockIdx.x * 128 + threadIdx.x;
    int y = blockIdx.y;
    int b = blockIdx.z;
    int p = y * WW + x;
    int i = b * HWN + p;

    // Fused zero-init of the accumulation buffer (consumed by splat_kernel,
    // ordered by the kernel boundary). Spare DRAM BW here absorbs it.
    g_acc[i] = make_float4(0.0f, 0.0f, 0.0f, 0.0f);

    float2 f = flow[i];
    Corners c = compute_corners(f.x, f.y, x, y);
    if (!c.valid) return;

    int base = b * HWN;
    #pragma unroll
    for (int j = 0; j < 4; j++) {
        if (c.k[j] >= 0.25f) {
            atomicMax(&g_dbuf[base + c.idx[j]], c.d);
        }
    }
}

// grid: (15, 1080, 4), block: 128
__global__ void __launch_bounds__(128) splat_kernel(const float* __restrict__ im0,
                                                    const float2* __restrict__ flow)
{
    int x = blockIdx.x * 128 + threadIdx.x;
    int y = blockIdx.y;
    int b = blockIdx.z;
    int p = y * WW + x;
    int i = b * HWN + p;

    float2 f = flow[i];
    Corners c = compute_corners(f.x, f.y, x, y);
    if (!c.valid) return;

    int base = b * HWN;
    const float* im0b = im0 + (size_t)b * CC * HWN + p;
    float v0 = __ldg(&im0b[0 * HWN]);
    float v1 = __ldg(&im0b[1 * HWN]);
    float v2 = __ldg(&im0b[2 * HWN]);

    #pragma unroll
    for (int j = 0; j < 4; j++) {
        float k = c.k[j];
        if (k >= 0.25f) {
            int ci = base + c.idx[j];
            int dg = g_dbuf[ci];
            if (dg - c.d <= MOTION_TH_I) {
                red_add_v4(&g_acc[ci], v0 * k, v1 * k, v2 * k, k);
            }
        }
    }
}

// 4 pixels per thread, vectorized. grid: (4, 1080, 4), block: 128 (512 >= 480 quads)
__global__ void __launch_bounds__(128) normalize_kernel(float* __restrict__ out)
{
    int q = blockIdx.x * 128 + threadIdx.x;   // quad index within row
    if (q >= WW / 4) return;
    int y = blockIdx.y;
    int b = blockIdx.z;
    int p = y * WW + q * 4;
    int i = b * HWN + p;

    float4 a0 = g_acc[i + 0];
    float4 a1 = g_acc[i + 1];
    float4 a2 = g_acc[i + 2];
    float4 a3 = g_acc[i + 3];

    float inv0 = 1.0f / fmaxf(a0.w * (1.0f / 3.0f), 1e-5f);
    float inv1 = 1.0f / fmaxf(a1.w * (1.0f / 3.0f), 1e-5f);
    float inv2 = 1.0f / fmaxf(a2.w * (1.0f / 3.0f), 1e-5f);
    float inv3 = 1.0f / fmaxf(a3.w * (1.0f / 3.0f), 1e-5f);

    float* outb = out + (size_t)b * CC * HWN + p;
    *(float4*)&outb[0 * HWN] = make_float4(a0.x * inv0, a1.x * inv1, a2.x * inv2, a3.x * inv3);
    *(float4*)&outb[1 * HWN] = make_float4(a0.y * inv0, a1.y * inv1, a2.y * inv2, a3.y * inv3);
    *(float4*)&outb[2 * HWN] = make_float4(a0.z * inv0, a1.z * inv1, a2.z * inv2, a3.z * inv3);
}

extern "C" void kernel_launch(void* const* d_in, const int* in_sizes, int n_in,
                              void* d_out, int out_size)
{
    const float*  im0  = (const float*)d_in[0];
    const float2* flow = (const float2*)d_in[1];
    float* out = (float*)d_out;

    void* pd = nullptr;
    cudaGetSymbolAddress(&pd, g_dbuf);
    cudaMemsetAsync(pd, 0, (size_t)NN * sizeof(int));

    dim3 blk(128, 1, 1);
    dim3 grd(WW / 128, HH, BB);          // 15 x 1080 x 4
    scatter_max_kernel<<<grd, blk>>>(flow);
    splat_kernel<<<grd, blk>>>(im0, flow);

    dim3 grdn((WW / 4 + 127) / 128, HH, BB);  // 4 x 1080 x 4
    normalize_kernel<<<grdn, blk>>>(out);
}

// round 4
// speedup vs baseline: 1.5456x; 1.0040x over previous
#include <cuda_runtime.h>
#include <cuda_bf16.h>
#include <math.h>

// Problem constants (fixed shapes from reference setup_inputs)
#define WW 1920
#define HH 1080
#define CC 3
#define BB 4
#define HWN (HH * WW)            // 2,073,600
#define NN  (BB * HWN)           // 8,294,400
#define MOTION_TH_I 25           // 0.25 * D_SCALE_INT

// Scratch (allocation-free rule: __device__ globals)
__device__ int    g_dbuf[NN];
__device__ float4 g_acc[NN];     // [c0, c1, c2, weight] per destination pixel

struct Corners {
    int   valid;      // 0/1
    int   d;          // depth int
    float k[4];       // nw, ne, sw, se
    int   idx[4];     // flat pixel index within batch image (y*W + x), clipped
};

__device__ __forceinline__ Corners compute_corners(float fx, float fy, int x, int y)
{
    Corners c;
    float xd = (float)x + fx;
    float yd = (float)y + fy;

    float magsq = fx * fx + fy * fy;
    c.d = (int)(100.0f * sqrtf(magsq));

    int xf = (int)floorf(xd);
    int yf = (int)floorf(yd);
    int xc = xf + 1;
    int yc = yf + 1;

    c.valid = (xf >= 0) & (xc <= WW) & (yf >= 0) & (yc <= HH);

    float xf_f = (float)xf, yf_f = (float)yf;
    float xc_f = (float)xc, yc_f = (float)yc;
    float wx1 = xc_f - xd;
    float wx0 = xd - xf_f;
    float wy1 = yc_f - yd;
    float wy0 = yd - yf_f;
    c.k[0] = wx1 * wy1;  // nw
    c.k[1] = wx0 * wy1;  // ne
    c.k[2] = wx1 * wy0;  // sw
    c.k[3] = wx0 * wy0;  // se

    int xfc = min(max(xf, 0), WW - 1);
    int yfc = min(max(yf, 0), HH - 1);
    int xcc = min(max(xc, 0), WW - 1);
    int ycc = min(max(yc, 0), HH - 1);
    c.idx[0] = yfc * WW + xfc;
    c.idx[1] = yfc * WW + xcc;
    c.idx[2] = ycc * WW + xfc;
    c.idx[3] = ycc * WW + xcc;
    return c;
}

__device__ __forceinline__ void red_add_v4(float4* addr, float a, float b, float cc, float dd)
{
    asm volatile("red.global.add.v4.f32 [%0], {%1, %2, %3, %4};"
                 :: "l"(addr), "f"(a), "f"(b), "f"(cc), "f"(dd)
                 : "memory");
}

// Per-batch kernels: pointers pre-offset to the batch slice.
// grid: (15, 1080), block: 128 -> x covers [0,1920) exactly, no guards.
__global__ void __launch_bounds__(128) scatter_max_kernel(const float2* __restrict__ flow,
                                                          int* __restrict__ dbuf)
{
    int x = blockIdx.x * 128 + threadIdx.x;
    int y = blockIdx.y;
    int p = y * WW + x;

    float2 f = flow[p];
    Corners c = compute_corners(f.x, f.y, x, y);
    if (!c.valid) return;

    #pragma unroll
    for (int j = 0; j < 4; j++) {
        if (c.k[j] >= 0.25f) {
            atomicMax(&dbuf[c.idx[j]], c.d);
        }
    }
}

__global__ void __launch_bounds__(128) splat_kernel(const float* __restrict__ im0,
                                                    const float2* __restrict__ flow,
                                                    const int* __restrict__ dbuf,
                                                    float4* __restrict__ acc)
{
    int x = blockIdx.x * 128 + threadIdx.x;
    int y = blockIdx.y;
    int p = y * WW + x;

    float2 f = flow[p];
    Corners c = compute_corners(f.x, f.y, x, y);
    if (!c.valid) return;

    float v0 = __ldg(&im0[0 * HWN + p]);
    float v1 = __ldg(&im0[1 * HWN + p]);
    float v2 = __ldg(&im0[2 * HWN + p]);

    #pragma unroll
    for (int j = 0; j < 4; j++) {
        float k = c.k[j];
        if (k >= 0.25f) {
            int ci = c.idx[j];
            int dg = dbuf[ci];
            if (dg - c.d <= MOTION_TH_I) {
                red_add_v4(&acc[ci], v0 * k, v1 * k, v2 * k, k);
            }
        }
    }
}

// 4 pixels per thread, vectorized. grid: (4, 1080), block: 128
__global__ void __launch_bounds__(128) normalize_kernel(const float4* __restrict__ acc,
                                                        float* __restrict__ out)
{
    int q = blockIdx.x * 128 + threadIdx.x;
    if (q >= WW / 4) return;
    int y = blockIdx.y;
    int p = y * WW + q * 4;

    float4 a0 = acc[p + 0];
    float4 a1 = acc[p + 1];
    float4 a2 = acc[p + 2];
    float4 a3 = acc[p + 3];

    float inv0 = 1.0f / fmaxf(a0.w * (1.0f / 3.0f), 1e-5f);
    float inv1 = 1.0f / fmaxf(a1.w * (1.0f / 3.0f), 1e-5f);
    float inv2 = 1.0f / fmaxf(a2.w * (1.0f / 3.0f), 1e-5f);
    float inv3 = 1.0f / fmaxf(a3.w * (1.0f / 3.0f), 1e-5f);

    *(float4*)&out[0 * HWN + p] = make_float4(a0.x * inv0, a1.x * inv1, a2.x * inv2, a3.x * inv3);
    *(float4*)&out[1 * HWN + p] = make_float4(a0.y * inv0, a1.y * inv1, a2.y * inv2, a3.y * inv3);
    *(float4*)&out[2 * HWN + p] = make_float4(a0.z * inv0, a1.z * inv1, a2.z * inv2, a3.z * inv3);
}

extern "C" void kernel_launch(void* const* d_in, const int* in_sizes, int n_in,
                              void* d_out, int out_size)
{
    const float*  im0  = (const float*)d_in[0];
    const float2* flow = (const float2*)d_in[1];
    float* out = (float*)d_out;

    // One-time creation of side streams/events (no device memory involved).
    static cudaStream_t s_side[BB - 1];
    static cudaEvent_t  e_fork;
    static cudaEvent_t  e_join[BB - 1];
    static bool s_init = [](){
        for (int i = 0; i < BB - 1; i++)
            cudaStreamCreateWithFlags(&s_side[i], cudaStreamNonBlocking);
        cudaEventCreateWithFlags(&e_fork, cudaEventDisableTiming);
        for (int i = 0; i < BB - 1; i++)
            cudaEventCreateWithFlags(&e_join[i], cudaEventDisableTiming);
        return true;
    }();
    (void)s_init;

    int*    dbuf = nullptr;
    float4* acc  = nullptr;
    {
        void *pd = nullptr, *pa = nullptr;
        cudaGetSymbolAddress(&pd, g_dbuf);
        cudaGetSymbolAddress(&pa, g_acc);
        dbuf = (int*)pd;
        acc  = (float4*)pa;
    }

    cudaStream_t main_s = 0;  // capture stream (legacy default)
    cudaEventRecord(e_fork, main_s);

    dim3 blk(128, 1, 1);
    dim3 grd(WW / 128, HH, 1);        // 15 x 1080
    dim3 grdn(WW / 4 / 128 + 1, HH, 1); // 4 x 1080

    for (int b = 0; b < BB; b++) {
        cudaStream_t st = (b == 0) ? main_s : s_side[b - 1];
        if (b != 0) cudaStreamWaitEvent(st, e_fork, 0);

        const float2* flow_b = flow + (size_t)b * HWN;
        const float*  im0_b  = im0  + (size_t)b * CC * HWN;
        float*        out_b  = out  + (size_t)b * CC * HWN;
        int*          dbuf_b = dbuf + (size_t)b * HWN;
        float4*       acc_b  = acc  + (size_t)b * HWN;

        cudaMemsetAsync(dbuf_b, 0, (size_t)HWN * sizeof(int), st);
        cudaMemsetAsync(acc_b,  0, (size_t)HWN * sizeof(float4), st);
        scatter_max_kernel<<<grd, blk, 0, st>>>(flow_b, dbuf_b);
        splat_kernel<<<grd, blk, 0, st>>>(im0_b, flow_b, dbuf_b, acc_b);
        normalize_kernel<<<grdn, blk, 0, st>>>(acc_b, out_b);

        if (b != 0) cudaEventRecord(e_join[b - 1], st);
    }
    for (int i = 0; i < BB - 1; i++)
        cudaStreamWaitEvent(main_s, e_join[i], 0);
}